// round 11
// baseline (speedup 1.0000x reference)
#include <cuda_runtime.h>

#define T_LEN   16777216
#define BLOCK   256
#define ITEMS   32
#define TILE    (BLOCK * ITEMS)          // 8192
#define NTILES  (T_LEN / TILE)           // 2048 = 1<<11
#define NT_LOG2 11
#define NWARP   (BLOCK / 32)
#define FULLMASK 0xffffffffu

// Decoupled-lookback state. NEVER reset: flags are generation-encoded
// (partial = 3*gen+1, inclusive = 3*gen+2, monotone across launches).
// gen = ticket >> 11 is identical for all CTAs of one launch.
__device__ unsigned g_ctr;
__device__ unsigned g_flag[NTILES];              // 0 init => stale for gen 0
__device__ float2   g_part[NTILES];              // (A, B) partial aggregate
__device__ float2   g_incl[NTILES];              // (A, B) inclusive prefix

__device__ __forceinline__ unsigned ld_acquire(const unsigned* p) {
    unsigned v;
    asm volatile("ld.acquire.gpu.global.b32 %0, [%1];" : "=r"(v) : "l"(p) : "memory");
    return v;
}
__device__ __forceinline__ void st_release(unsigned* p, unsigned v) {
    asm volatile("st.release.gpu.global.b32 [%0], %1;" :: "l"(p), "r"(v) : "memory");
}

__global__ __launch_bounds__(BLOCK) void ses_scan(
    const float* __restrict__ y, const float* __restrict__ alpha_p,
    float* __restrict__ out)
{
    // Padded transpose buffer: float4 slot = Q + (Q>>3) for quad index Q.
    // Conflict-free for striped (consecutive Q) and blocked (Q = 8*tid+i).
    __shared__ float sbuf[TILE + TILE / 8];      // 36 KB
    __shared__ float sh_wB[NWARP];
    __shared__ float sh_carry;
    __shared__ unsigned sh_ticket;

    const int tid  = threadIdx.x;
    const int lane = tid & 31;
    const int wid  = tid >> 5;

    // Dynamic tile ids, increasing within a launch -> lookback never deadlocks.
    if (tid == 0) sh_ticket = atomicAdd(&g_ctr, 1u);
    __syncthreads();
    const unsigned ticket = sh_ticket;
    const int tile = (int)(ticket & (NTILES - 1u));
    const unsigned fPart = 3u * (ticket >> NT_LOG2) + 1u;   // this gen's partial
    const unsigned fIncl = fPart + 1u;                      // this gen's inclusive

    const float alpha = __ldg(alpha_p);
    const float a = 1.0f - alpha;

    float4* s4 = reinterpret_cast<float4*>(sbuf);

    // ---- phase 1: striped coalesced load -> padded SMEM ----
    {
        const float4* yin = reinterpret_cast<const float4*>(y) + (size_t)tile * (TILE / 4);
        #pragma unroll
        for (int j = 0; j < 8; j++) {
            const int Q = j * BLOCK + tid;
            s4[Q + (Q >> 3)] = yin[Q];
        }
    }
    __syncthreads();

    // ---- phase 2: blocked read + thread-local serial scan (zero carry-in) ----
    float v[ITEMS];
    #pragma unroll
    for (int i = 0; i < 8; i++) {
        const int Q = 8 * tid + i;
        float4 q = s4[Q + (Q >> 3)];
        v[4*i+0] = q.x; v[4*i+1] = q.y; v[4*i+2] = q.z; v[4*i+3] = q.w;
    }

    // element t: (a, alpha*y_t); global t=0 pinned to (0, y_0)
    float B;
    {
        float p = 0.f;
        const bool first = (tile == 0 && tid == 0);
        #pragma unroll
        for (int i = 0; i < ITEMS; i++) {
            float aa = a, bb = alpha * v[i];
            if (first && i == 0) { aa = 0.f; bb = v[0]; }
            p = fmaf(aa, p, bb);
            v[i] = p;
        }
        B = p;
    }

    float a2 = a*a, a4 = a2*a2, a8 = a4*a4, a16 = a8*a8;
    const float a32 = a16 * a16;

    // ---- warp inclusive scan of B; window-A closed form a^(32d) ----
    float m = a32;
    #pragma unroll
    for (int d = 1; d < 32; d <<= 1) {
        float pB = __shfl_up_sync(FULLMASK, B, d);
        if (lane >= d) B = fmaf(m, pB, B);
        m = m * m;
    }
    const float A1024 = m;                       // a^1024 = per-warp A
    float exB = __shfl_up_sync(FULLMASK, B, 1);
    if (lane == 0) exB = 0.f;
    if (lane == 31) sh_wB[wid] = B;
    __syncthreads();

    // cross-warp B prefix over warps 0..wid-1
    float WB = 0.f;
    #pragma unroll
    for (int w = 0; w < NWARP; w++) if (w < wid) WB = fmaf(A1024, WB, sh_wB[w]);

    // exA = a^(32*lane)
    float exA = 1.f;
    { float bp = a32; int e = lane;
      #pragma unroll
      for (int k = 0; k < 5; k++) { if (e & 1) exA *= bp; bp *= bp; e >>= 1; } }
    const float TexB = fmaf(exA, WB, exB);
    float TexA = exA;                            // a^(32*tid); multiplies carry only
    { float wp = A1024; int e = wid;
      #pragma unroll
      for (int k = 0; k < 3; k++) { if (e & 1) TexA *= wp; wp *= wp; e >>= 1; } }

    // ---- publish tile aggregate: weak stcg data, RELEASE flag (no fence/atomic) ----
    float aggA = 0.f, aggB = 0.f;                // tid-0 registers
    if (tid == 0) {
        float gB = 0.f;
        #pragma unroll
        for (int w = 0; w < NWARP; w++) gB = fmaf(A1024, gB, sh_wB[w]);
        float A8192 = A1024 * A1024; A8192 *= A8192; A8192 *= A8192;
        aggA = (tile == 0) ? 0.f : A8192;        // tile 0 truly has A = 0
        aggB = gB;
        if (tile == 0) {
            __stcg(&g_incl[0], make_float2(0.f, gB));
            st_release(&g_flag[0], fIncl);
            sh_carry = 0.f;
        } else {
            __stcg(&g_part[tile], make_float2(A8192, gB));
            st_release(&g_flag[tile], fPart);
        }
    }

    // ---- warp-parallel decoupled lookback (warp 0), early-exit on accA==0 ----
    if (wid == 0 && tile > 0) {
        __syncwarp();
        float accA = 1.f, accB = 0.f;
        int pred = tile - 1;
        for (;;) {
            const int idx = pred - lane;         // lane 0 = latest predecessor
            unsigned st = 2u;
            if (idx >= 0) {
                unsigned f = ld_acquire(&g_flag[idx]);
                while (f < fPart) {              // stale gen or unset
                    __nanosleep(32);
                    f = ld_acquire(&g_flag[idx]);
                }
                st = f - fPart + 1u;             // 1=partial 2=inclusive
            }
            float mA, mB;
            if (idx < 0) { mA = 1.f; mB = 0.f; }
            else {
                float2 d = (st == 2u) ? __ldcg(&g_incl[idx]) : __ldcg(&g_part[idx]);
                mA = d.x; mB = d.y;
            }

            const unsigned bal = __ballot_sync(FULLMASK, st == 2u);
            const int mm = bal ? (__ffs(bal) - 1) : 32;
            const int start = (mm < 32) ? mm : 31;

            // window combine earliest->latest: c = combine(c, s_L)
            float cA = 1.f, cB = 0.f;
            for (int L = start; L >= 0; --L) {
                float sA = __shfl_sync(FULLMASK, mA, L);
                float sB = __shfl_sync(FULLMASK, mB, L);
                cB = fmaf(sA, cB, sB);
                cA = cA * sA;
            }
            float nB = fmaf(accA, cB, accB);     // acc = combine(window, acc)
            accA = cA * accA;
            accB = nB;

            if (mm < 32 || accA == 0.0f) break;  // accA==0: exact independence
            pred -= 32;
        }
        if (lane == 0) {
            __stcg(&g_incl[tile], make_float2(accA * aggA, fmaf(aggA, accB, aggB)));
            st_release(&g_flag[tile], fIncl);
            sh_carry = accB;                     // level just before this tile
        }
    }
    __syncthreads();

    // ---- fixup ----
    const float c = fmaf(TexA, sh_carry, TexB);
    {
        float cp = c * a;
        #pragma unroll
        for (int i = 0; i < ITEMS; i++) { v[i] += cp; cp *= a; }
    }

    // ---- phase 3: blocked -> SMEM, striped streaming stores ----
    #pragma unroll
    for (int i = 0; i < 8; i++) {
        const int Q = 8 * tid + i;
        s4[Q + (Q >> 3)] = make_float4(v[4*i+0], v[4*i+1], v[4*i+2], v[4*i+3]);
    }
    __syncthreads();

    {
        float4* o4 = reinterpret_cast<float4*>(out) + (size_t)tile * (TILE / 4);
        if (tile != NTILES - 1) {
            #pragma unroll
            for (int j = 0; j < 8; j++) {
                const int Q = j * BLOCK + tid;
                __stcs(&o4[Q], s4[Q + (Q >> 3)]);
            }
        } else {
            // last tile: output length T_LEN-1, never write index T_LEN-1
            const long long tbase = (long long)tile * TILE;
            #pragma unroll
            for (int j = 0; j < 8; j++) {
                const int Q = j * BLOCK + tid;
                float4 q = s4[Q + (Q >> 3)];
                const long long g = tbase + 4LL * Q;
                if (g + 4 <= (long long)(T_LEN - 1)) {
                    __stcs(&o4[Q], q);
                } else {
                    float* op = out + g;
                    if (g + 0 < (long long)(T_LEN - 1)) op[0] = q.x;
                    if (g + 1 < (long long)(T_LEN - 1)) op[1] = q.y;
                    if (g + 2 < (long long)(T_LEN - 1)) op[2] = q.z;
                    if (g + 3 < (long long)(T_LEN - 1)) op[3] = q.w;
                }
            }
        }
    }
}

extern "C" void kernel_launch(void* const* d_in, const int* in_sizes, int n_in,
                              void* d_out, int out_size) {
    const float* y     = (const float*)d_in[0];   // timeseries, T_LEN fp32
    const float* alpha = (const float*)d_in[1];   // 1 fp32
    float* out = (float*)d_out;                   // T_LEN-1 fp32
    (void)in_sizes; (void)n_in; (void)out_size;

    ses_scan<<<NTILES, BLOCK>>>(y, alpha, out);   // single launch, no init pass
}